// round 8
// baseline (speedup 1.0000x reference)
#include <cuda_runtime.h>
#include <cuda_fp16.h>
#include <cstdint>

#define N_NODES 8192
#define D_IN    128
#define D_OUT   128

// ---------------- device scratch (static, allocation-free) ----------------
__device__ float  g_dinv[N_NODES];
__device__ __half g_Bh[(size_t)D_OUT * N_NODES];       // B^T: [128][8192] K-major fp16, dinv-scaled
__device__ float  g_part[(size_t)N_NODES * D_OUT];     // accumulated output (pre row-scale)

__device__ __forceinline__ uint32_t smem_u32(const void* p) {
    uint32_t a;
    asm("{ .reg .u64 t; cvta.to.shared.u64 t, %1; cvt.u32.u64 %0, t; }" : "=r"(a) : "l"(p));
    return a;
}
__device__ __forceinline__ void cp_async16(uint32_t dst, const void* src) {
    asm volatile("cp.async.cg.shared.global [%0], [%1], 16;" :: "r"(dst), "l"(src));
}
#define CP_COMMIT() asm volatile("cp.async.commit_group;" ::: "memory")

__device__ __forceinline__ uint32_t pack_h2(float lo, float hi) {
    uint32_t r;
    asm("cvt.rn.f16x2.f32 %0, %1, %2;" : "=r"(r) : "f"(hi), "f"(lo));
    return r;
}
__device__ __forceinline__ void mma_f16_16x8x16(float c[4], uint32_t a0, uint32_t a1, uint32_t a2, uint32_t a3,
                                                uint32_t b0, uint32_t b1) {
    asm volatile(
        "mma.sync.aligned.m16n8k16.row.col.f32.f16.f16.f32 "
        "{%0,%1,%2,%3}, {%4,%5,%6,%7}, {%8,%9}, {%0,%1,%2,%3};"
        : "+f"(c[0]), "+f"(c[1]), "+f"(c[2]), "+f"(c[3])
        : "r"(a0), "r"(a1), "r"(a2), "r"(a3), "r"(b0), "r"(b1));
}
__device__ __forceinline__ void ldsm_x4(uint32_t r[4], uint32_t addr) {
    asm volatile("ldmatrix.sync.aligned.m8n8.x4.shared.b16 {%0,%1,%2,%3}, [%4];"
        : "=r"(r[0]), "=r"(r[1]), "=r"(r[2]), "=r"(r[3]) : "r"(addr));
}

// ================= kernel 1: row sums -> dinv (read-only) =================
__global__ void rowsum_kernel(const float* __restrict__ A) {
    int row = blockIdx.x;
    const float4* arow = reinterpret_cast<const float4*>(A + (size_t)row * N_NODES);
    float4 v[8];
    #pragma unroll
    for (int i = 0; i < 8; ++i) v[i] = __ldcs(&arow[threadIdx.x + i * 256]);
    float s = 0.f;
    #pragma unroll
    for (int i = 0; i < 8; ++i) s += (v[i].x + v[i].y) + (v[i].z + v[i].w);
    #pragma unroll
    for (int o = 16; o; o >>= 1) s += __shfl_xor_sync(0xffffffffu, s, o);
    __shared__ float ws[8];
    if ((threadIdx.x & 31) == 0) ws[threadIdx.x >> 5] = s;
    __syncthreads();
    if (threadIdx.x < 8) {
        float t = ws[threadIdx.x];
        #pragma unroll
        for (int o = 4; o; o >>= 1) t += __shfl_xor_sync(0xffu, t, o);
        if (threadIdx.x == 0) g_dinv[row] = 1.0f / (sqrtf(t) + 1e-8f);
    }
}

// ============ kernel 2: B^T[o][j] = fp16( dinv[j] * (V@W + b)[j][o] ) ============
__global__ void fc_kernel(const float* __restrict__ values, const float* __restrict__ W,
                          const float* __restrict__ bvec) {
    int tid = threadIdx.x;
    int o = tid & 127;
    int half_idx = tid >> 7;
    int j0 = blockIdx.x * 32 + half_idx * 16;
    float acc[16];
    #pragma unroll
    for (int i = 0; i < 16; ++i) acc[i] = 0.f;
    const float* vbase = values + (size_t)j0 * D_IN;
    for (int k = 0; k < D_IN; k += 4) {
        float w0 = W[(k + 0) * D_OUT + o];
        float w1 = W[(k + 1) * D_OUT + o];
        float w2 = W[(k + 2) * D_OUT + o];
        float w3 = W[(k + 3) * D_OUT + o];
        #pragma unroll
        for (int jj = 0; jj < 16; ++jj) {
            float4 v = *reinterpret_cast<const float4*>(vbase + jj * D_IN + k);
            acc[jj] = fmaf(v.x, w0, fmaf(v.y, w1, fmaf(v.z, w2, fmaf(v.w, w3, acc[jj]))));
        }
    }
    float bo = bvec[o];
    uint32_t packed[8];
    #pragma unroll
    for (int p = 0; p < 8; ++p) {
        float y0 = (acc[2 * p]     + bo) * g_dinv[j0 + 2 * p];
        float y1 = (acc[2 * p + 1] + bo) * g_dinv[j0 + 2 * p + 1];
        packed[p] = pack_h2(y0, y1);
    }
    uint4* dst = reinterpret_cast<uint4*>(g_Bh + (size_t)o * N_NODES + j0);
    dst[0] = make_uint4(packed[0], packed[1], packed[2], packed[3]);
    dst[1] = make_uint4(packed[4], packed[5], packed[6], packed[7]);
}

// ================= kernel 3: balanced persistent GEMM, fp32 A converted in-SMEM =================
// Work unit = (rowblock 128 rows, BK=32 K-chunk): 64 x 256 = 16384 units over 148 CTAs.
// A: cp.async fp32 into 4-deep staging; converted to fp16 operand one iter ahead of use.
// B: cp.async fp16 (4-deep). k-half warps accumulate independently; atomicAdd flush.
#define BM 128
#define BK 32
#define NBUF 4
#define PITCH32 144                   // 128B fp32 data + 16B pad
#define PITCH16 80                    // 64B fp16 data + 16B pad
#define A32_BYTES (128 * PITCH32)     // 18432
#define A16_BYTES (128 * PITCH16)     // 10240
#define B16_BYTES (128 * PITCH16)     // 10240
#define OFF_A16 (NBUF * A32_BYTES)            // 73728
#define OFF_B16 (OFF_A16 + 2 * A16_BYTES)     // 94208
#define GEMM_SMEM (OFF_B16 + NBUF * B16_BYTES) // 135168
#define NCTA 148
#define TOTAL_UNITS 16384

__device__ __forceinline__ void load_stage(int u, int buf, int tid, uint32_t smem_base) {
    const int row_base = (u >> 8) * BM;
    const size_t kk = (size_t)(u & 255) * BK;
    #pragma unroll
    for (int i = 0; i < 6; ++i) {
        int c = tid + i * 256;            // 0..1535 16B chunks
        if (c < 1024) {                   // A fp32: 128 rows x 128B
            int row = c >> 3, h = c & 7;
            cp_async16(smem_base + (uint32_t)buf * A32_BYTES + (uint32_t)(row * PITCH32 + h * 16),
                       /* src fp32 */ (const void*)0 /* patched below */);
        }
    }
}

// (load_stage split into A/B explicit versions to keep src pointers simple)
__device__ __forceinline__ void load_unit(int u, int buf, int tid, uint32_t smem_base,
                                          const float* __restrict__ A) {
    const int row_base = (u >> 8) * BM;
    const size_t kk = (size_t)(u & 255) * BK;
    #pragma unroll
    for (int i = 0; i < 4; ++i) {         // A fp32: 1024 chunks
        int c = tid + i * 256;
        int row = c >> 3, h = c & 7;
        cp_async16(smem_base + (uint32_t)buf * A32_BYTES + (uint32_t)(row * PITCH32 + h * 16),
                   A + (size_t)(row_base + row) * N_NODES + kk + (size_t)h * 4);
    }
    #pragma unroll
    for (int i = 0; i < 2; ++i) {         // B fp16: 512 chunks
        int c = tid + i * 256;
        int row = c >> 2, h = c & 3;
        cp_async16(smem_base + OFF_B16 + (uint32_t)buf * B16_BYTES + (uint32_t)(row * PITCH16 + h * 16),
                   g_Bh + (size_t)row * N_NODES + kk + (size_t)h * 8);
    }
}

__device__ __forceinline__ void convert_A(int buf32, int buf16, int tid, uint32_t smem_base) {
    const int row = tid >> 1;
    const int half = tid & 1;
    const uint32_t src = smem_base + (uint32_t)buf32 * A32_BYTES + (uint32_t)(row * PITCH32 + half * 64);
    float f[16];
    #pragma unroll
    for (int i = 0; i < 4; ++i)
        asm volatile("ld.shared.v4.f32 {%0,%1,%2,%3}, [%4];"
            : "=f"(f[4*i]), "=f"(f[4*i+1]), "=f"(f[4*i+2]), "=f"(f[4*i+3])
            : "r"(src + i * 16));
    uint32_t u[8];
    #pragma unroll
    for (int i = 0; i < 8; ++i) u[i] = pack_h2(f[2*i], f[2*i+1]);
    const uint32_t dst = smem_base + OFF_A16 + (uint32_t)buf16 * A16_BYTES
                       + (uint32_t)(row * PITCH16 + half * 32);
    asm volatile("st.shared.v4.b32 [%0], {%1,%2,%3,%4};" :: "r"(dst),
        "r"(u[0]), "r"(u[1]), "r"(u[2]), "r"(u[3]) : "memory");
    asm volatile("st.shared.v4.b32 [%0], {%1,%2,%3,%4};" :: "r"(dst + 16),
        "r"(u[4]), "r"(u[5]), "r"(u[6]), "r"(u[7]) : "memory");
}

__global__ void __launch_bounds__(256, 1)
gemm_kernel(const float* __restrict__ A) {
    extern __shared__ float smem[];
    const uint32_t smem_base = smem_u32(smem);
    const int tid = threadIdx.x;
    const int lane = tid & 31;
    const int wid = tid >> 5;
    const int wm = wid & 1;               // 2 warps in m (64 rows)
    const int wn = (wid >> 1) & 1;        // 2 warps in n (64 cols)
    const int kh = wid >> 2;              // 2 warps in k (k16 halves of BK=32)
    const int g  = lane >> 2;
    const int tg = lane & 3;

    // balanced contiguous ranges: 104 CTAs x 111 units, 44 x 110
    const int cta = blockIdx.x;
    const int start = cta * 110 + min(cta, 104);
    const int count = 110 + (cta < 104 ? 1 : 0);

    const int aOff = (wm * 64 + ((lane >> 3) & 1) * 8 + (lane & 7)) * PITCH16
                   + (lane >> 4) * 16 + kh * 32;
    const int bOff = (wn * 64 + ((lane >> 4) & 1) * 8 + (lane & 7)) * PITCH16
                   + ((lane >> 3) & 1) * 16 + kh * 32;

    float c[4][8][4];
    #pragma unroll
    for (int mi = 0; mi < 4; ++mi)
        #pragma unroll
        for (int ni = 0; ni < 8; ++ni)
            #pragma unroll
            for (int q = 0; q < 4; ++q) c[mi][ni][q] = 0.f;

    // prologue: load units 0,1,2; convert unit 0
    load_unit(start, 0, tid, smem_base, A);     CP_COMMIT();
    load_unit(start + 1, 1, tid, smem_base, A); CP_COMMIT();
    load_unit(start + 2, 2, tid, smem_base, A); CP_COMMIT();
    asm volatile("cp.async.wait_group 2;" ::: "memory");   // unit 0 landed
    __syncthreads();
    convert_A(0, 0, tid, smem_base);
    __syncthreads();

    for (int j = 0; j < count; ++j) {
        const int u = start + j;

        // rowblock boundary: flush previous rowblock's accumulators (registers only)
        if (j > 0 && (u & 255) == 0) {
            const int prb = (u - 1) >> 8;
            #pragma unroll
            for (int mi = 0; mi < 4; ++mi) {
                const int r0 = prb * BM + wm * 64 + mi * 16 + g;
                #pragma unroll
                for (int ni = 0; ni < 8; ++ni) {
                    const int col = wn * 64 + ni * 8 + 2 * tg;
                    atomicAdd(g_part + (size_t)r0 * D_OUT + col,           c[mi][ni][0]);
                    atomicAdd(g_part + (size_t)r0 * D_OUT + col + 1,       c[mi][ni][1]);
                    atomicAdd(g_part + (size_t)(r0 + 8) * D_OUT + col,     c[mi][ni][2]);
                    atomicAdd(g_part + (size_t)(r0 + 8) * D_OUT + col + 1, c[mi][ni][3]);
                    c[mi][ni][0] = c[mi][ni][1] = c[mi][ni][2] = c[mi][ni][3] = 0.f;
                }
            }
        }

        asm volatile("cp.async.wait_group 1;" ::: "memory");  // unit j+1 landed
        __syncthreads();   // A16[(j+1)&1] safe to overwrite; A32[j+1], B16[j] visible

        if (j + 3 < count) load_unit(u + 3, (j + 3) % NBUF, tid, smem_base, A);
        CP_COMMIT();

        if (j + 1 < count) convert_A((j + 1) % NBUF, (j + 1) & 1, tid, smem_base);

        const uint32_t smA = smem_base + OFF_A16 + (uint32_t)(j & 1) * A16_BYTES;
        const uint32_t smB = smem_base + OFF_B16 + (uint32_t)(j % NBUF) * B16_BYTES;

        uint32_t a[4][4], b[4][4];
        #pragma unroll
        for (int mi = 0; mi < 4; ++mi)
            ldsm_x4(a[mi], smA + (uint32_t)(aOff + mi * 16 * PITCH16));
        #pragma unroll
        for (int cb = 0; cb < 4; ++cb)
            ldsm_x4(b[cb], smB + (uint32_t)(bOff + cb * 16 * PITCH16));
        #pragma unroll
        for (int mi = 0; mi < 4; ++mi) {
            #pragma unroll
            for (int ni = 0; ni < 8; ++ni) {
                mma_f16_16x8x16(c[mi][ni], a[mi][0], a[mi][1], a[mi][2], a[mi][3],
                                b[ni >> 1][(ni & 1) * 2], b[ni >> 1][(ni & 1) * 2 + 1]);
            }
        }
    }

    // final flush
    {
        const int prb = (start + count - 1) >> 8;
        #pragma unroll
        for (int mi = 0; mi < 4; ++mi) {
            const int r0 = prb * BM + wm * 64 + mi * 16 + g;
            #pragma unroll
            for (int ni = 0; ni < 8; ++ni) {
                const int col = wn * 64 + ni * 8 + 2 * tg;
                atomicAdd(g_part + (size_t)r0 * D_OUT + col,           c[mi][ni][0]);
                atomicAdd(g_part + (size_t)r0 * D_OUT + col + 1,       c[mi][ni][1]);
                atomicAdd(g_part + (size_t)(r0 + 8) * D_OUT + col,     c[mi][ni][2]);
                atomicAdd(g_part + (size_t)(r0 + 8) * D_OUT + col + 1, c[mi][ni][3]);
            }
        }
    }
}

// ================= kernel 4: out = dinv[row] * g_part =================
__global__ void reduce_kernel(float* __restrict__ out) {
    int i = blockIdx.x * 256 + threadIdx.x;
    const float4 p = reinterpret_cast<const float4*>(g_part)[i];
    int row = (i * 4) >> 7;
    float s = g_dinv[row];
    float4 r;
    r.x = s * p.x;
    r.y = s * p.y;
    r.z = s * p.z;
    r.w = s * p.w;
    reinterpret_cast<float4*>(out)[i] = r;
}

// ================= launch =================
extern "C" void kernel_launch(void* const* d_in, const int* in_sizes, int n_in,
                              void* d_out, int out_size) {
    const float* values = (const float*)d_in[0];
    const float* A      = (const float*)d_in[1];
    const float* W      = (const float*)d_in[2];
    const float* b      = (const float*)d_in[3];
    float* out = (float*)d_out;

    void* part_ptr = nullptr;
    cudaGetSymbolAddress(&part_ptr, g_part);
    cudaMemsetAsync(part_ptr, 0, (size_t)N_NODES * D_OUT * sizeof(float));

    rowsum_kernel<<<N_NODES, 256>>>(A);
    fc_kernel<<<N_NODES / 32, 256>>>(values, W, b);
    cudaFuncSetAttribute(gemm_kernel, cudaFuncAttributeMaxDynamicSharedMemorySize, GEMM_SMEM);
    gemm_kernel<<<NCTA, 256, GEMM_SMEM>>>(A);
    reduce_kernel<<<(N_NODES * D_OUT / 4) / 256, 256>>>(out);
}

// round 9
// speedup vs baseline: 1.1027x; 1.1027x over previous
#include <cuda_runtime.h>
#include <cuda_fp16.h>
#include <cstdint>

#define N_NODES 8192
#define D_IN    128
#define D_OUT   128

// ---------------- device scratch (static, allocation-free) ----------------
__device__ float  g_dinv[N_NODES];
__device__ __half g_Bh[(size_t)D_OUT * N_NODES];       // B^T: [128][8192] K-major fp16, dinv-scaled
__device__ float  g_part[2][(size_t)N_NODES * D_OUT];  // K-split partial outputs

__device__ __forceinline__ uint32_t smem_u32(const void* p) {
    uint32_t a;
    asm("{ .reg .u64 t; cvta.to.shared.u64 t, %1; cvt.u32.u64 %0, t; }" : "=r"(a) : "l"(p));
    return a;
}
__device__ __forceinline__ void cp_async16(uint32_t dst, const void* src) {
    asm volatile("cp.async.cg.shared.global [%0], [%1], 16;" :: "r"(dst), "l"(src));
}
#define CP_COMMIT() asm volatile("cp.async.commit_group;" ::: "memory")

__device__ __forceinline__ uint32_t pack_h2(float lo, float hi) {
    uint32_t r;
    asm("cvt.rn.f16x2.f32 %0, %1, %2;" : "=r"(r) : "f"(hi), "f"(lo));
    return r;
}
__device__ __forceinline__ float2 lds_f2(uint32_t addr) {
    float2 v;
    asm volatile("ld.shared.v2.f32 {%0,%1}, [%2];" : "=f"(v.x), "=f"(v.y) : "r"(addr));
    return v;
}
__device__ __forceinline__ void mma_f16_16x8x16(float c[4], uint32_t a0, uint32_t a1, uint32_t a2, uint32_t a3,
                                                uint32_t b0, uint32_t b1) {
    asm volatile(
        "mma.sync.aligned.m16n8k16.row.col.f32.f16.f16.f32 "
        "{%0,%1,%2,%3}, {%4,%5,%6,%7}, {%8,%9}, {%0,%1,%2,%3};"
        : "+f"(c[0]), "+f"(c[1]), "+f"(c[2]), "+f"(c[3])
        : "r"(a0), "r"(a1), "r"(a2), "r"(a3), "r"(b0), "r"(b1));
}
__device__ __forceinline__ void ldsm_x4(uint32_t r[4], uint32_t addr) {
    asm volatile("ldmatrix.sync.aligned.m8n8.x4.shared.b16 {%0,%1,%2,%3}, [%4];"
        : "=r"(r[0]), "=r"(r[1]), "=r"(r[2]), "=r"(r[3]) : "r"(addr));
}

// ================= kernel 1: row sums -> dinv (read-only) =================
__global__ void rowsum_kernel(const float* __restrict__ A) {
    int row = blockIdx.x;
    const float4* arow = reinterpret_cast<const float4*>(A + (size_t)row * N_NODES);
    float4 v[8];
    #pragma unroll
    for (int i = 0; i < 8; ++i) v[i] = __ldcs(&arow[threadIdx.x + i * 256]);
    float s = 0.f;
    #pragma unroll
    for (int i = 0; i < 8; ++i) s += (v[i].x + v[i].y) + (v[i].z + v[i].w);
    #pragma unroll
    for (int o = 16; o; o >>= 1) s += __shfl_xor_sync(0xffffffffu, s, o);
    __shared__ float ws[8];
    if ((threadIdx.x & 31) == 0) ws[threadIdx.x >> 5] = s;
    __syncthreads();
    if (threadIdx.x < 8) {
        float t = ws[threadIdx.x];
        #pragma unroll
        for (int o = 4; o; o >>= 1) t += __shfl_xor_sync(0xffu, t, o);
        if (threadIdx.x == 0) g_dinv[row] = 1.0f / (sqrtf(t) + 1e-8f);
    }
}

// ============ kernel 2: B^T[o][j] = fp16( dinv[j] * (V@W + b)[j][o] ) ============
__global__ void fc_kernel(const float* __restrict__ values, const float* __restrict__ W,
                          const float* __restrict__ bvec) {
    int tid = threadIdx.x;
    int o = tid & 127;
    int half_idx = tid >> 7;
    int j0 = blockIdx.x * 32 + half_idx * 16;
    float acc[16];
    #pragma unroll
    for (int i = 0; i < 16; ++i) acc[i] = 0.f;
    const float* vbase = values + (size_t)j0 * D_IN;
    for (int k = 0; k < D_IN; k += 4) {
        float w0 = W[(k + 0) * D_OUT + o];
        float w1 = W[(k + 1) * D_OUT + o];
        float w2 = W[(k + 2) * D_OUT + o];
        float w3 = W[(k + 3) * D_OUT + o];
        #pragma unroll
        for (int jj = 0; jj < 16; ++jj) {
            float4 v = *reinterpret_cast<const float4*>(vbase + jj * D_IN + k);
            acc[jj] = fmaf(v.x, w0, fmaf(v.y, w1, fmaf(v.z, w2, fmaf(v.w, w3, acc[jj]))));
        }
    }
    float bo = bvec[o];
    uint32_t packed[8];
    #pragma unroll
    for (int p = 0; p < 8; ++p) {
        float y0 = (acc[2 * p]     + bo) * g_dinv[j0 + 2 * p];
        float y1 = (acc[2 * p + 1] + bo) * g_dinv[j0 + 2 * p + 1];
        packed[p] = pack_h2(y0, y1);
    }
    uint4* dst = reinterpret_cast<uint4*>(g_Bh + (size_t)o * N_NODES + j0);
    dst[0] = make_uint4(packed[0], packed[1], packed[2], packed[3]);
    dst[1] = make_uint4(packed[4], packed[5], packed[6], packed[7]);
}

// ================= kernel 3: partial = A[rows, khalf] @ B[khalf, :] =================
// CTA 128x128, BK=32, 8 warps 2m x 2n x 2k. A kept fp32 in smem (cp.async);
// fragments loaded via ld.shared.v2.f32 + cvt to fp16 in registers (no fp16 staging).
// B fp16 via cp.async + ldmatrix. k-half accumulators merged through smem at epilogue.
#define BM 128
#define BK 32
#define STAGES 3
#define PITCH32 160                   // fp32 A rows: 128B data + 32B pad (40 words ≡ 8 mod 32)
#define PITCH16 80                    // fp16 B rows: 64B data + 16B pad
#define A32_BYTES (128 * PITCH32)     // 20480
#define B16_BYTES (128 * PITCH16)     // 10240
#define STAGE_BYTES (A32_BYTES + B16_BYTES)   // 30720
#define GEMM_SMEM (STAGES * STAGE_BYTES)      // 92160
#define KSPLIT 2
#define KPER (N_NODES / KSPLIT)       // 4096
#define ITERS (KPER / BK)             // 128

__device__ __forceinline__ void load_stage(int it, int buf, int tid, int row_base, size_t k0,
                                           const float* __restrict__ A, uint32_t smem_base) {
    const size_t kk = k0 + (size_t)it * BK;
    const uint32_t sbase = smem_base + (uint32_t)buf * STAGE_BYTES;
    #pragma unroll
    for (int i = 0; i < 4; ++i) {         // A fp32: 128 rows x 8 16B-chunks
        int c = tid + i * 256;
        int row = c >> 3, h = c & 7;
        cp_async16(sbase + (uint32_t)(row * PITCH32 + h * 16),
                   A + (size_t)(row_base + row) * N_NODES + kk + (size_t)h * 4);
    }
    #pragma unroll
    for (int i = 0; i < 2; ++i) {         // B fp16: 128 rows x 4 16B-chunks
        int c = tid + i * 256;
        int row = c >> 2, h = c & 3;
        cp_async16(sbase + A32_BYTES + (uint32_t)(row * PITCH16 + h * 16),
                   g_Bh + (size_t)row * N_NODES + kk + (size_t)h * 8);
    }
}

__global__ void __launch_bounds__(256, 1)
gemm_kernel(const float* __restrict__ A) {
    extern __shared__ float smem[];
    const uint32_t smem_base = smem_u32(smem);
    const int tid = threadIdx.x;
    const int lane = tid & 31;
    const int wid = tid >> 5;
    const int wm = wid & 1;               // 2 warps in m (64 rows)
    const int wn = (wid >> 1) & 1;        // 2 warps in n (64 cols)
    const int kh = wid >> 2;              // 2 warps in k (k16 halves of BK=32)
    const int g  = lane >> 2;
    const int tg = lane & 3;
    const int row_base = blockIdx.x * BM;
    const int ksplit = blockIdx.y;
    const size_t k0 = (size_t)ksplit * KPER;

    // A fragment lane address (fp32): row = wm*64 + mi*16 + g (+8), col = kh*16 + 2tg (+8)
    const uint32_t aBase = (uint32_t)((wm * 64 + g) * PITCH32 + (kh * 16 + 2 * tg) * 4);
    // B fragment lane address (fp16 ldmatrix)
    const int bOff = (wn * 64 + ((lane >> 4) & 1) * 8 + (lane & 7)) * PITCH16
                   + ((lane >> 3) & 1) * 16 + kh * 32;

    float c[4][8][4];
    #pragma unroll
    for (int mi = 0; mi < 4; ++mi)
        #pragma unroll
        for (int ni = 0; ni < 8; ++ni)
            #pragma unroll
            for (int q = 0; q < 4; ++q) c[mi][ni][q] = 0.f;

    #pragma unroll
    for (int s = 0; s < STAGES - 1; ++s) {
        load_stage(s, s, tid, row_base, k0, A, smem_base);
        CP_COMMIT();
    }

    for (int it = 0; it < ITERS; ++it) {
        asm volatile("cp.async.wait_group %0;" :: "n"(STAGES - 2) : "memory");
        __syncthreads();

        int nxt = it + STAGES - 1;
        if (nxt < ITERS) load_stage(nxt, nxt % STAGES, tid, row_base, k0, A, smem_base);
        CP_COMMIT();

        const uint32_t smA = smem_base + (uint32_t)(it % STAGES) * STAGE_BYTES;
        const uint32_t smB = smA + A32_BYTES;

        // A fragments: fp32 LDS pairs -> cvt to f16x2 in registers
        uint32_t a[4][4];
        #pragma unroll
        for (int mi = 0; mi < 4; ++mi) {
            const uint32_t r0 = smA + aBase + (uint32_t)(mi * 16 * PITCH32);
            float2 v0 = lds_f2(r0);                            // (g,    k0:k1)
            float2 v1 = lds_f2(r0 + 8 * PITCH32);              // (g+8,  k0:k1)
            float2 v2 = lds_f2(r0 + 32);                       // (g,    k8:k9)
            float2 v3 = lds_f2(r0 + 8 * PITCH32 + 32);         // (g+8,  k8:k9)
            a[mi][0] = pack_h2(v0.x, v0.y);
            a[mi][1] = pack_h2(v1.x, v1.y);
            a[mi][2] = pack_h2(v2.x, v2.y);
            a[mi][3] = pack_h2(v3.x, v3.y);
        }
        uint32_t b[4][4];
        #pragma unroll
        for (int cb = 0; cb < 4; ++cb)
            ldsm_x4(b[cb], smB + (uint32_t)(bOff + cb * 16 * PITCH16));

        #pragma unroll
        for (int mi = 0; mi < 4; ++mi) {
            #pragma unroll
            for (int ni = 0; ni < 8; ++ni) {
                mma_f16_16x8x16(c[mi][ni], a[mi][0], a[mi][1], a[mi][2], a[mi][3],
                                b[ni >> 1][(ni & 1) * 2], b[ni >> 1][(ni & 1) * 2 + 1]);
            }
        }
    }

    // ---- epilogue: merge k-half partials through smem, then store ----
    __syncthreads();   // stage buffers dead; reuse first 64KB for merge
    const uint32_t pairBase = smem_base + (uint32_t)(wid & 3) * 16384u;
    if (kh == 1) {
        #pragma unroll
        for (int mi = 0; mi < 4; ++mi)
            #pragma unroll
            for (int ni = 0; ni < 8; ++ni) {
                uint32_t off = pairBase + (uint32_t)(((mi * 8 + ni) * 32 + lane) * 16);
                asm volatile("st.shared.v4.b32 [%0], {%1,%2,%3,%4};" :: "r"(off),
                    "r"(__float_as_uint(c[mi][ni][0])), "r"(__float_as_uint(c[mi][ni][1])),
                    "r"(__float_as_uint(c[mi][ni][2])), "r"(__float_as_uint(c[mi][ni][3])) : "memory");
            }
    }
    __syncthreads();
    if (kh == 0) {
        float* P = g_part[ksplit];
        #pragma unroll
        for (int mi = 0; mi < 4; ++mi) {
            const int r0 = row_base + wm * 64 + mi * 16 + g;
            #pragma unroll
            for (int ni = 0; ni < 8; ++ni) {
                uint32_t off = pairBase + (uint32_t)(((mi * 8 + ni) * 32 + lane) * 16);
                float4 p;
                asm volatile("ld.shared.v4.f32 {%0,%1,%2,%3}, [%4];"
                    : "=f"(p.x), "=f"(p.y), "=f"(p.z), "=f"(p.w) : "r"(off));
                const int col = wn * 64 + ni * 8 + 2 * tg;
                float2 lo = make_float2(c[mi][ni][0] + p.x, c[mi][ni][1] + p.y);
                float2 hi = make_float2(c[mi][ni][2] + p.z, c[mi][ni][3] + p.w);
                *reinterpret_cast<float2*>(P + (size_t)r0 * D_OUT + col) = lo;
                *reinterpret_cast<float2*>(P + (size_t)(r0 + 8) * D_OUT + col) = hi;
            }
        }
    }
}

// ================= kernel 4: out = dinv[row] * (part0 + part1) =================
__global__ void reduce_kernel(float* __restrict__ out) {
    int i = blockIdx.x * 256 + threadIdx.x;
    const float4 p0 = reinterpret_cast<const float4*>(g_part[0])[i];
    const float4 p1 = reinterpret_cast<const float4*>(g_part[1])[i];
    int row = (i * 4) >> 7;
    float s = g_dinv[row];
    float4 r;
    r.x = s * (p0.x + p1.x);
    r.y = s * (p0.y + p1.y);
    r.z = s * (p0.z + p1.z);
    r.w = s * (p0.w + p1.w);
    reinterpret_cast<float4*>(out)[i] = r;
}

// ================= launch =================
extern "C" void kernel_launch(void* const* d_in, const int* in_sizes, int n_in,
                              void* d_out, int out_size) {
    const float* values = (const float*)d_in[0];
    const float* A      = (const float*)d_in[1];
    const float* W      = (const float*)d_in[2];
    const float* b      = (const float*)d_in[3];
    float* out = (float*)d_out;

    rowsum_kernel<<<N_NODES, 256>>>(A);
    fc_kernel<<<N_NODES / 32, 256>>>(values, W, b);
    cudaFuncSetAttribute(gemm_kernel, cudaFuncAttributeMaxDynamicSharedMemorySize, GEMM_SMEM);
    gemm_kernel<<<dim3(N_NODES / BM, KSPLIT), 256, GEMM_SMEM>>>(A);
    reduce_kernel<<<(N_NODES * D_OUT / 4) / 256, 256>>>(out);
}

// round 10
// speedup vs baseline: 1.1097x; 1.0063x over previous
#include <cuda_runtime.h>
#include <cuda_fp16.h>
#include <cstdint>

#define N_NODES 8192
#define D_IN    128
#define D_OUT   128

// ---------------- device scratch (static, allocation-free) ----------------
__device__ float  g_dinv[N_NODES];
__device__ __half g_Bh[(size_t)D_OUT * N_NODES];       // B^T: [128][8192] K-major fp16, dinv-scaled

__device__ __forceinline__ uint32_t smem_u32(const void* p) {
    uint32_t a;
    asm("{ .reg .u64 t; cvta.to.shared.u64 t, %1; cvt.u32.u64 %0, t; }" : "=r"(a) : "l"(p));
    return a;
}
__device__ __forceinline__ void cp_async16(uint32_t dst, const void* src) {
    asm volatile("cp.async.cg.shared.global [%0], [%1], 16;" :: "r"(dst), "l"(src));
}
#define CP_COMMIT() asm volatile("cp.async.commit_group;" ::: "memory")

__device__ __forceinline__ uint32_t pack_h2(float lo, float hi) {
    uint32_t r;
    asm("cvt.rn.f16x2.f32 %0, %1, %2;" : "=r"(r) : "f"(hi), "f"(lo));
    return r;
}
__device__ __forceinline__ float2 lds_f2(uint32_t addr) {
    float2 v;
    asm volatile("ld.shared.v2.f32 {%0,%1}, [%2];" : "=f"(v.x), "=f"(v.y) : "r"(addr));
    return v;
}
__device__ __forceinline__ void mma_f16_16x8x16(float c[4], uint32_t a0, uint32_t a1, uint32_t a2, uint32_t a3,
                                                uint32_t b0, uint32_t b1) {
    asm volatile(
        "mma.sync.aligned.m16n8k16.row.col.f32.f16.f16.f32 "
        "{%0,%1,%2,%3}, {%4,%5,%6,%7}, {%8,%9}, {%0,%1,%2,%3};"
        : "+f"(c[0]), "+f"(c[1]), "+f"(c[2]), "+f"(c[3])
        : "r"(a0), "r"(a1), "r"(a2), "r"(a3), "r"(b0), "r"(b1));
}
__device__ __forceinline__ void ldsm_x4(uint32_t r[4], uint32_t addr) {
    asm volatile("ldmatrix.sync.aligned.m8n8.x4.shared.b16 {%0,%1,%2,%3}, [%4];"
        : "=r"(r[0]), "=r"(r[1]), "=r"(r[2]), "=r"(r[3]) : "r"(addr));
}

// ================= kernel 1: row sums -> dinv (read-only) =================
__global__ void rowsum_kernel(const float* __restrict__ A) {
    int row = blockIdx.x;
    const float4* arow = reinterpret_cast<const float4*>(A + (size_t)row * N_NODES);
    float4 v[8];
    #pragma unroll
    for (int i = 0; i < 8; ++i) v[i] = __ldcs(&arow[threadIdx.x + i * 256]);
    float s = 0.f;
    #pragma unroll
    for (int i = 0; i < 8; ++i) s += (v[i].x + v[i].y) + (v[i].z + v[i].w);
    #pragma unroll
    for (int o = 16; o; o >>= 1) s += __shfl_xor_sync(0xffffffffu, s, o);
    __shared__ float ws[8];
    if ((threadIdx.x & 31) == 0) ws[threadIdx.x >> 5] = s;
    __syncthreads();
    if (threadIdx.x < 8) {
        float t = ws[threadIdx.x];
        #pragma unroll
        for (int o = 4; o; o >>= 1) t += __shfl_xor_sync(0xffu, t, o);
        if (threadIdx.x == 0) g_dinv[row] = 1.0f / (sqrtf(t) + 1e-8f);
    }
}

// ============ kernel 2: B^T[o][j] = fp16( dinv[j] * (V@W + b)[j][o] ) ============
__global__ void fc_kernel(const float* __restrict__ values, const float* __restrict__ W,
                          const float* __restrict__ bvec) {
    int tid = threadIdx.x;
    int o = tid & 127;
    int half_idx = tid >> 7;
    int j0 = blockIdx.x * 32 + half_idx * 16;
    float acc[16];
    #pragma unroll
    for (int i = 0; i < 16; ++i) acc[i] = 0.f;
    const float* vbase = values + (size_t)j0 * D_IN;
    for (int k = 0; k < D_IN; k += 4) {
        float w0 = W[(k + 0) * D_OUT + o];
        float w1 = W[(k + 1) * D_OUT + o];
        float w2 = W[(k + 2) * D_OUT + o];
        float w3 = W[(k + 3) * D_OUT + o];
        #pragma unroll
        for (int jj = 0; jj < 16; ++jj) {
            float4 v = *reinterpret_cast<const float4*>(vbase + jj * D_IN + k);
            acc[jj] = fmaf(v.x, w0, fmaf(v.y, w1, fmaf(v.z, w2, fmaf(v.w, w3, acc[jj]))));
        }
    }
    float bo = bvec[o];
    uint32_t packed[8];
    #pragma unroll
    for (int p = 0; p < 8; ++p) {
        float y0 = (acc[2 * p]     + bo) * g_dinv[j0 + 2 * p];
        float y1 = (acc[2 * p + 1] + bo) * g_dinv[j0 + 2 * p + 1];
        packed[p] = pack_h2(y0, y1);
    }
    uint4* dst = reinterpret_cast<uint4*>(g_Bh + (size_t)o * N_NODES + j0);
    dst[0] = make_uint4(packed[0], packed[1], packed[2], packed[3]);
    dst[1] = make_uint4(packed[4], packed[5], packed[6], packed[7]);
}

// ===== kernel 3: balanced persistent GEMM; fp32 A, in-register cvt; fused scaled flush =====
// Work unit = (rowblock 128 rows, BK=32 chunk): 64 x 256 = 16384 units over 148 CTAs,
// contiguous ranges. 8 warps 2m x 2n x 2k. Accumulators flushed at rowblock boundaries
// straight into out via atomicAdd, scaled by dinv[row] (k-half warps add independently).
#define BM 128
#define BK 32
#define STAGES 3
#define PITCH32 160                   // fp32 A rows: 128B data + 32B pad
#define PITCH16 80                    // fp16 B rows: 64B data + 16B pad
#define A32_BYTES (128 * PITCH32)     // 20480
#define B16_BYTES (128 * PITCH16)     // 10240
#define STAGE_BYTES (A32_BYTES + B16_BYTES)   // 30720
#define GEMM_SMEM (STAGES * STAGE_BYTES)      // 92160
#define NCTA 148

__device__ __forceinline__ void load_unit(int u, int buf, int tid,
                                          const float* __restrict__ A, uint32_t smem_base) {
    const int row_base = (u >> 8) * BM;
    const size_t kk = (size_t)(u & 255) * BK;
    const uint32_t sbase = smem_base + (uint32_t)buf * STAGE_BYTES;
    #pragma unroll
    for (int i = 0; i < 4; ++i) {         // A fp32: 128 rows x 8 16B-chunks
        int c = tid + i * 256;
        int row = c >> 3, h = c & 7;
        cp_async16(sbase + (uint32_t)(row * PITCH32 + h * 16),
                   A + (size_t)(row_base + row) * N_NODES + kk + (size_t)h * 4);
    }
    #pragma unroll
    for (int i = 0; i < 2; ++i) {         // B fp16: 128 rows x 4 16B-chunks
        int c = tid + i * 256;
        int row = c >> 2, h = c & 3;
        cp_async16(sbase + A32_BYTES + (uint32_t)(row * PITCH16 + h * 16),
                   g_Bh + (size_t)row * N_NODES + kk + (size_t)h * 8);
    }
}

__global__ void __launch_bounds__(256, 1)
gemm_kernel(const float* __restrict__ A, float* __restrict__ out) {
    extern __shared__ float smem[];
    const uint32_t smem_base = smem_u32(smem);
    const int tid = threadIdx.x;
    const int lane = tid & 31;
    const int wid = tid >> 5;
    const int wm = wid & 1;               // 2 warps in m (64 rows)
    const int wn = (wid >> 1) & 1;        // 2 warps in n (64 cols)
    const int kh = wid >> 2;              // 2 warps in k (k16 halves of BK=32)
    const int g  = lane >> 2;
    const int tg = lane & 3;

    // balanced contiguous ranges: 104 CTAs x 111 units, 44 x 110
    const int cta = blockIdx.x;
    const int start = cta * 110 + min(cta, 104);
    const int count = 110 + (cta < 104 ? 1 : 0);

    const uint32_t aBase = (uint32_t)((wm * 64 + g) * PITCH32 + (kh * 16 + 2 * tg) * 4);
    const int bOff = (wn * 64 + ((lane >> 4) & 1) * 8 + (lane & 7)) * PITCH16
                   + ((lane >> 3) & 1) * 16 + kh * 32;

    float c[4][8][4];
    #pragma unroll
    for (int mi = 0; mi < 4; ++mi)
        #pragma unroll
        for (int ni = 0; ni < 8; ++ni)
            #pragma unroll
            for (int q = 0; q < 4; ++q) c[mi][ni][q] = 0.f;

    load_unit(start, 0, tid, A, smem_base);     CP_COMMIT();
    load_unit(start + 1, 1, tid, A, smem_base); CP_COMMIT();

    for (int j = 0; j < count; ++j) {
        const int u = start + j;

        // rowblock boundary: flush previous rowblock's accumulators (dinv-scaled atomics)
        if (j > 0 && (u & 255) == 0) {
            const int prb = (u - 1) >> 8;
            #pragma unroll
            for (int mi = 0; mi < 4; ++mi) {
                const int r0 = prb * BM + wm * 64 + mi * 16 + g;
                const float s0 = g_dinv[r0];
                const float s1 = g_dinv[r0 + 8];
                #pragma unroll
                for (int ni = 0; ni < 8; ++ni) {
                    const int col = wn * 64 + ni * 8 + 2 * tg;
                    atomicAdd(out + (size_t)r0 * D_OUT + col,           s0 * c[mi][ni][0]);
                    atomicAdd(out + (size_t)r0 * D_OUT + col + 1,       s0 * c[mi][ni][1]);
                    atomicAdd(out + (size_t)(r0 + 8) * D_OUT + col,     s1 * c[mi][ni][2]);
                    atomicAdd(out + (size_t)(r0 + 8) * D_OUT + col + 1, s1 * c[mi][ni][3]);
                    c[mi][ni][0] = c[mi][ni][1] = c[mi][ni][2] = c[mi][ni][3] = 0.f;
                }
            }
        }

        asm volatile("cp.async.wait_group %0;" :: "n"(STAGES - 2) : "memory");
        __syncthreads();

        if (j + 2 < count) load_unit(u + 2, (j + 2) % STAGES, tid, A, smem_base);
        CP_COMMIT();

        const uint32_t smA = smem_base + (uint32_t)(j % STAGES) * STAGE_BYTES;
        const uint32_t smB = smA + A32_BYTES;

        uint32_t a[4][4];
        #pragma unroll
        for (int mi = 0; mi < 4; ++mi) {
            const uint32_t r0 = smA + aBase + (uint32_t)(mi * 16 * PITCH32);
            float2 v0 = lds_f2(r0);
            float2 v1 = lds_f2(r0 + 8 * PITCH32);
            float2 v2 = lds_f2(r0 + 32);
            float2 v3 = lds_f2(r0 + 8 * PITCH32 + 32);
            a[mi][0] = pack_h2(v0.x, v0.y);
            a[mi][1] = pack_h2(v1.x, v1.y);
            a[mi][2] = pack_h2(v2.x, v2.y);
            a[mi][3] = pack_h2(v3.x, v3.y);
        }
        uint32_t b[4][4];
        #pragma unroll
        for (int cb = 0; cb < 4; ++cb)
            ldsm_x4(b[cb], smB + (uint32_t)(bOff + cb * 16 * PITCH16));

        #pragma unroll
        for (int mi = 0; mi < 4; ++mi) {
            #pragma unroll
            for (int ni = 0; ni < 8; ++ni) {
                mma_f16_16x8x16(c[mi][ni], a[mi][0], a[mi][1], a[mi][2], a[mi][3],
                                b[ni >> 1][(ni & 1) * 2], b[ni >> 1][(ni & 1) * 2 + 1]);
            }
        }
    }

    // final flush
    {
        const int prb = (start + count - 1) >> 8;
        #pragma unroll
        for (int mi = 0; mi < 4; ++mi) {
            const int r0 = prb * BM + wm * 64 + mi * 16 + g;
            const float s0 = g_dinv[r0];
            const float s1 = g_dinv[r0 + 8];
            #pragma unroll
            for (int ni = 0; ni < 8; ++ni) {
                const int col = wn * 64 + ni * 8 + 2 * tg;
                atomicAdd(out + (size_t)r0 * D_OUT + col,           s0 * c[mi][ni][0]);
                atomicAdd(out + (size_t)r0 * D_OUT + col + 1,       s0 * c[mi][ni][1]);
                atomicAdd(out + (size_t)(r0 + 8) * D_OUT + col,     s1 * c[mi][ni][2]);
                atomicAdd(out + (size_t)(r0 + 8) * D_OUT + col + 1, s1 * c[mi][ni][3]);
            }
        }
    }
}

// ================= launch =================
extern "C" void kernel_launch(void* const* d_in, const int* in_sizes, int n_in,
                              void* d_out, int out_size) {
    const float* values = (const float*)d_in[0];
    const float* A      = (const float*)d_in[1];
    const float* W      = (const float*)d_in[2];
    const float* b      = (const float*)d_in[3];
    float* out = (float*)d_out;

    cudaMemsetAsync(out, 0, (size_t)out_size * sizeof(float));
    rowsum_kernel<<<N_NODES, 256>>>(A);
    fc_kernel<<<N_NODES / 32, 256>>>(values, W, b);
    cudaFuncSetAttribute(gemm_kernel, cudaFuncAttributeMaxDynamicSharedMemorySize, GEMM_SMEM);
    gemm_kernel<<<NCTA, 256, GEMM_SMEM>>>(A, out);
}